// round 7
// baseline (speedup 1.0000x reference)
#include <cuda_runtime.h>

// Problem shape (fixed by the dataset):
//   z:      (4096, 1, 64, 128) f32  -> row of 8192 floats per batch entry
//   ch_ids: (4096,) int32 or int64, values in [0, 32)
//   out:    (4096, 128, 128) f32    -> first 8192 = z row, last 8192 = channel mean
#define BATCH   4096
#define NCH     32
#define ZROW    8192u
#define OROW    16384u
#define NTHR    512                    // 4 row-groups x 128 lanes
#define NGRP    4
#define CHUNK   512u                   // floats per block slice (128 lanes * float4)
#define NCHUNK  16                     // ZROW / CHUNK

// ---------------------------------------------------------------------------
// Build the row list for channel c: 16 warps scan all 4096 ids (prefetched to
// registers). Two ballot passes (count, then rank+scatter) keep register
// pressure low for the 32-reg / 4-blocks-per-SM budget. Fixed (warp, round,
// lane) order -> deterministic. rows[] is ushort (b < 4096).
// dtype probe: ch_ids may be int32 or int64 (JAX x64 flag). Interpret as
// int32[]; if the first 128 odd words are all zero it's int64 (values < 32).
// ---------------------------------------------------------------------------
__device__ __forceinline__ int build_rows_full(const int* __restrict__ ids32,
                                               int c, unsigned short* rows,
                                               int tid) {
    __shared__ int segcnt[17];
    __shared__ int segoff[16];

    const int lane = tid & 31;
    const int w    = tid >> 5;                 // 16 warps

    int stride;                                // warp-uniform probe
    {
        const int x = ids32[2 * lane + 1] | ids32[2 * (lane + 32) + 1];
        const unsigned nz = __ballot_sync(0xffffffffu, x != 0);
        stride = (nz == 0) ? 2 : 1;
    }

    const int base = w * 256;                  // warp covers 256 ids
    int myid[8];
    #pragma unroll
    for (int r = 0; r < 8; ++r)
        myid[r] = ids32[(base + r * 32 + lane) * stride];

    // pass 1: count only
    int count = 0;
    #pragma unroll
    for (int r = 0; r < 8; ++r)
        count += __popc(__ballot_sync(0xffffffffu, myid[r] == c));
    if (lane == 0) segcnt[w] = count;
    __syncthreads();

    if (w == 0) {                              // prefix over 16 warp-segments
        int v = (lane < 16) ? segcnt[lane] : 0;
        int incl = v;
        #pragma unroll
        for (int d = 1; d < 16; d <<= 1) {
            const int t = __shfl_up_sync(0xffffffffu, incl, d);
            if (lane >= d) incl += t;
        }
        if (lane < 16) segoff[lane] = incl - v;
        if (lane == 15) segcnt[16] = incl;
    }
    __syncthreads();

    // pass 2: recompute ballots, scatter
    int pos = segoff[w];
    #pragma unroll
    for (int r = 0; r < 8; ++r) {
        const unsigned mk = __ballot_sync(0xffffffffu, myid[r] == c);
        if (myid[r] == c)
            rows[pos + __popc(mk & ((1u << lane) - 1u))] =
                (unsigned short)(base + r * 32 + lane);
        pos += __popc(mk);
    }
    const int total = segcnt[16];
    __syncthreads();
    return total;
}

// ---------------------------------------------------------------------------
// Single fused kernel. grid = (NCHUNK, NCH), block = 512, 4 blocks/SM.
// Group g (128 lanes) handles rows g, g+4, ... of channel c:
//   phase 2: load z slice (streaming), write top-half copy, accumulate
//   phase 3: smem reduce across the 4 groups (fixed order) -> channel mean
//   phase 4: write bottom-half mean slice for the same rows
// ---------------------------------------------------------------------------
__global__ void __launch_bounds__(NTHR, 4)
mix_kernel(const float* __restrict__ z, float* __restrict__ out,
           const int* __restrict__ ids) {
    __shared__ unsigned short rows[BATCH];   // 8 KB
    __shared__ float4 red[NGRP][128];        // 8 KB cross-group reduce

    const int chunk = blockIdx.x;
    const int c     = blockIdx.y;
    const int tid   = threadIdx.x;

    const int m = build_rows_full(ids, c, rows, tid);

    const int      g   = tid >> 7;           // row-group 0..3
    const int      l   = tid & 127;          // lane within group
    const unsigned off = (unsigned)chunk * CHUNK + (unsigned)l * 4u;

    // phase 2: copy + partial accumulate (rows g, g+4, ...)
    const int nb = (m > g) ? (m - g + NGRP - 1) / NGRP : 0;
    float4 acc = make_float4(0.f, 0.f, 0.f, 0.f);
    int j = 0;
    for (; j + 4 <= nb; j += 4) {
        const unsigned b0 = rows[g + NGRP * (j + 0)];
        const unsigned b1 = rows[g + NGRP * (j + 1)];
        const unsigned b2 = rows[g + NGRP * (j + 2)];
        const unsigned b3 = rows[g + NGRP * (j + 3)];
        const float4 v0 = __ldcs((const float4*)(z + b0 * ZROW + off));
        const float4 v1 = __ldcs((const float4*)(z + b1 * ZROW + off));
        const float4 v2 = __ldcs((const float4*)(z + b2 * ZROW + off));
        const float4 v3 = __ldcs((const float4*)(z + b3 * ZROW + off));
        __stcs((float4*)(out + b0 * OROW + off), v0);
        __stcs((float4*)(out + b1 * OROW + off), v1);
        __stcs((float4*)(out + b2 * OROW + off), v2);
        __stcs((float4*)(out + b3 * OROW + off), v3);
        acc.x += (v0.x + v1.x) + (v2.x + v3.x);
        acc.y += (v0.y + v1.y) + (v2.y + v3.y);
        acc.z += (v0.z + v1.z) + (v2.z + v3.z);
        acc.w += (v0.w + v1.w) + (v2.w + v3.w);
    }
    for (; j < nb; ++j) {
        const unsigned b = rows[g + NGRP * j];
        const float4 v = __ldcs((const float4*)(z + b * ZROW + off));
        __stcs((float4*)(out + b * OROW + off), v);
        acc.x += v.x; acc.y += v.y; acc.z += v.z; acc.w += v.w;
    }

    // phase 3: cross-group reduce (deterministic fixed order)
    red[g][l] = acc;
    __syncthreads();
    const float4 p0 = red[0][l];
    const float4 p1 = red[1][l];
    const float4 p2 = red[2][l];
    const float4 p3 = red[3][l];
    const float inv = 1.0f / (float)(m > 0 ? m : 1);
    float4 mn;
    mn.x = ((p0.x + p1.x) + (p2.x + p3.x)) * inv;
    mn.y = ((p0.y + p1.y) + (p2.y + p3.y)) * inv;
    mn.z = ((p0.z + p1.z) + (p2.z + p3.z)) * inv;
    mn.w = ((p0.w + p1.w) + (p2.w + p3.w)) * inv;

    // phase 4: broadcast mean slice to bottom half of the same rows
    j = 0;
    for (; j + 4 <= nb; j += 4) {
        const unsigned b0 = rows[g + NGRP * (j + 0)];
        const unsigned b1 = rows[g + NGRP * (j + 1)];
        const unsigned b2 = rows[g + NGRP * (j + 2)];
        const unsigned b3 = rows[g + NGRP * (j + 3)];
        __stcs((float4*)(out + b0 * OROW + ZROW + off), mn);
        __stcs((float4*)(out + b1 * OROW + ZROW + off), mn);
        __stcs((float4*)(out + b2 * OROW + ZROW + off), mn);
        __stcs((float4*)(out + b3 * OROW + ZROW + off), mn);
    }
    for (; j < nb; ++j) {
        const unsigned b = rows[g + NGRP * j];
        __stcs((float4*)(out + b * OROW + ZROW + off), mn);
    }
}

extern "C" void kernel_launch(void* const* d_in, const int* in_sizes, int n_in,
                              void* d_out, int out_size) {
    const float* z   = (const float*)d_in[0];
    const int*   ids = (const int*)d_in[1];
    float*       out = (float*)d_out;

    dim3 grid(NCHUNK, NCH);
    mix_kernel<<<grid, NTHR>>>(z, out, ids);
}

// round 8
// speedup vs baseline: 1.1695x; 1.1695x over previous
#include <cuda_runtime.h>

// Problem shape (fixed by the dataset):
//   z:      (4096, 1, 64, 128) f32  -> row of 8192 floats per batch entry
//   ch_ids: (4096,) int32 or int64, values in [0, 32)
//   out:    (4096, 128, 128) f32    -> first 8192 = z row, last 8192 = channel mean
#define BATCH   4096
#define NCH     32
#define ZROW    8192u
#define OROW    16384u
#define NTHR    256                    // 2 row-groups x 128 lanes
#define NGRP    2
#define CHUNK   512u                   // floats per block slice (128 lanes * float4)
#define NCHUNK  16                     // ZROW / CHUNK

// ---------------------------------------------------------------------------
// Build the row list for channel c: 8 warps scan all 4096 ids (prefetched to
// registers, 16 ballot rounds each). Two passes (count, then rank+scatter).
// Fixed (warp, round, lane) order -> deterministic. rows[] is ushort.
// dtype probe: ch_ids may be int32 or int64 (JAX x64 flag). Interpret as
// int32[]; if the first 128 odd words are all zero it's int64 (values < 32).
// ---------------------------------------------------------------------------
__device__ __forceinline__ int build_rows_full(const int* __restrict__ ids32,
                                               int c, unsigned short* rows,
                                               int tid) {
    __shared__ int segcnt[9];
    __shared__ int segoff[8];

    const int lane = tid & 31;
    const int w    = tid >> 5;                 // 8 warps

    int stride;                                // warp-uniform probe
    {
        const int x = ids32[2 * lane + 1] | ids32[2 * (lane + 32) + 1];
        const unsigned nz = __ballot_sync(0xffffffffu, x != 0);
        stride = (nz == 0) ? 2 : 1;
    }

    const int base = w * 512;                  // warp covers 512 ids
    int myid[16];
    #pragma unroll
    for (int r = 0; r < 16; ++r)
        myid[r] = ids32[(base + r * 32 + lane) * stride];

    // pass 1: count only
    int count = 0;
    #pragma unroll
    for (int r = 0; r < 16; ++r)
        count += __popc(__ballot_sync(0xffffffffu, myid[r] == c));
    if (lane == 0) segcnt[w] = count;
    __syncthreads();

    if (w == 0) {                              // prefix over 8 warp-segments
        int v = (lane < 8) ? segcnt[lane] : 0;
        int incl = v;
        #pragma unroll
        for (int d = 1; d < 8; d <<= 1) {
            const int t = __shfl_up_sync(0xffffffffu, incl, d);
            if (lane >= d) incl += t;
        }
        if (lane < 8) segoff[lane] = incl - v;
        if (lane == 7) segcnt[8] = incl;
    }
    __syncthreads();

    // pass 2: recompute ballots, scatter
    int pos = segoff[w];
    #pragma unroll
    for (int r = 0; r < 16; ++r) {
        const unsigned mk = __ballot_sync(0xffffffffu, myid[r] == c);
        if (myid[r] == c)
            rows[pos + __popc(mk & ((1u << lane) - 1u))] =
                (unsigned short)(base + r * 32 + lane);
        pos += __popc(mk);
    }
    const int total = segcnt[8];
    __syncthreads();
    return total;
}

// ---------------------------------------------------------------------------
// Single fused kernel. grid = (NCHUNK, NCH) = 512 blocks, 256 thr, ~6/SM
// -> all blocks resident in ONE wave. Group g (128 lanes) handles rows
// g, g+2, ... of channel c:
//   phase 2: load z slice, write top-half copy, accumulate partial sum
//   phase 3: smem reduce across the 2 groups (fixed order) -> channel mean
//   phase 4: write bottom-half mean slice for the same rows
// ---------------------------------------------------------------------------
__global__ void __launch_bounds__(NTHR)
mix_kernel(const float* __restrict__ z, float* __restrict__ out,
           const int* __restrict__ ids) {
    __shared__ unsigned short rows[BATCH];   // 8 KB
    __shared__ float4 red[NGRP][128];        // 4 KB cross-group reduce

    const int chunk = blockIdx.x;
    const int c     = blockIdx.y;
    const int tid   = threadIdx.x;

    const int m = build_rows_full(ids, c, rows, tid);

    const int      g   = tid >> 7;           // row-group 0..1
    const int      l   = tid & 127;          // lane within group
    const unsigned off = (unsigned)chunk * CHUNK + (unsigned)l * 4u;

    // phase 2: copy + partial accumulate (rows g, g+2, ...)
    const int nb = (m > g) ? (m - g + NGRP - 1) / NGRP : 0;
    float4 acc = make_float4(0.f, 0.f, 0.f, 0.f);
    int j = 0;
    for (; j + 4 <= nb; j += 4) {
        const unsigned b0 = rows[g + NGRP * (j + 0)];
        const unsigned b1 = rows[g + NGRP * (j + 1)];
        const unsigned b2 = rows[g + NGRP * (j + 2)];
        const unsigned b3 = rows[g + NGRP * (j + 3)];
        const float4 v0 = *(const float4*)(z + b0 * ZROW + off);
        const float4 v1 = *(const float4*)(z + b1 * ZROW + off);
        const float4 v2 = *(const float4*)(z + b2 * ZROW + off);
        const float4 v3 = *(const float4*)(z + b3 * ZROW + off);
        *(float4*)(out + b0 * OROW + off) = v0;
        *(float4*)(out + b1 * OROW + off) = v1;
        *(float4*)(out + b2 * OROW + off) = v2;
        *(float4*)(out + b3 * OROW + off) = v3;
        acc.x += (v0.x + v1.x) + (v2.x + v3.x);
        acc.y += (v0.y + v1.y) + (v2.y + v3.y);
        acc.z += (v0.z + v1.z) + (v2.z + v3.z);
        acc.w += (v0.w + v1.w) + (v2.w + v3.w);
    }
    for (; j < nb; ++j) {
        const unsigned b = rows[g + NGRP * j];
        const float4 v = *(const float4*)(z + b * ZROW + off);
        *(float4*)(out + b * OROW + off) = v;
        acc.x += v.x; acc.y += v.y; acc.z += v.z; acc.w += v.w;
    }

    // phase 3: cross-group reduce (deterministic fixed order)
    red[g][l] = acc;
    __syncthreads();
    const float4 p0 = red[0][l];
    const float4 p1 = red[1][l];
    const float inv = 1.0f / (float)(m > 0 ? m : 1);
    float4 mn;
    mn.x = (p0.x + p1.x) * inv;
    mn.y = (p0.y + p1.y) * inv;
    mn.z = (p0.z + p1.z) * inv;
    mn.w = (p0.w + p1.w) * inv;

    // phase 4: broadcast mean slice to bottom half of the same rows
    j = 0;
    for (; j + 4 <= nb; j += 4) {
        const unsigned b0 = rows[g + NGRP * (j + 0)];
        const unsigned b1 = rows[g + NGRP * (j + 1)];
        const unsigned b2 = rows[g + NGRP * (j + 2)];
        const unsigned b3 = rows[g + NGRP * (j + 3)];
        *(float4*)(out + b0 * OROW + ZROW + off) = mn;
        *(float4*)(out + b1 * OROW + ZROW + off) = mn;
        *(float4*)(out + b2 * OROW + ZROW + off) = mn;
        *(float4*)(out + b3 * OROW + ZROW + off) = mn;
    }
    for (; j < nb; ++j) {
        const unsigned b = rows[g + NGRP * j];
        *(float4*)(out + b * OROW + ZROW + off) = mn;
    }
}

extern "C" void kernel_launch(void* const* d_in, const int* in_sizes, int n_in,
                              void* d_out, int out_size) {
    const float* z   = (const float*)d_in[0];
    const int*   ids = (const int*)d_in[1];
    float*       out = (float*)d_out;

    dim3 grid(NCHUNK, NCH);
    mix_kernel<<<grid, NTHR>>>(z, out, ids);
}